// round 9
// baseline (speedup 1.0000x reference)
#include <cuda_runtime.h>
#include <cuda_bf16.h>
#include <cstdint>

// ---------------------------------------------------------------------------
// Problem constants
//   x: [1024, 512, 128] fp32 -> logits [1024, 100] fp32
// ---------------------------------------------------------------------------
#define B_SZ    1024
#define T_STEPS 512
#define I_DIM   128
#define H_DIM   64
#define G_DIM   256                   // 4*H gate columns
#define E_DIM   128
#define C_DIM   100
#define M_ROWS  (B_SZ * T_STEPS)      // 524288

// ---------------------------------------------------------------------------
// Scratch (allocations forbidden -> __device__ globals, referenced directly
// from device code; no host symbol lookups needed)
// ---------------------------------------------------------------------------
__device__ float g_xg[(size_t)M_ROWS * G_DIM];    // 512 MB, reused by both layers
__device__ float g_out1[(size_t)M_ROWS * H_DIM];  // 128 MB, layer-0 hidden sequence
__device__ float g_hlast[B_SZ * H_DIM];           // layer-1 final hidden
// Pre-swizzled tf32 B-fragments (hi/lo) for the two input GEMMs.
// Layout per (g, kit): 128 floats = [hi: lane*2+{0,1}][lo: 64 + lane*2+{0,1}]
__device__ float g_bfrag0[32 * 16 * 128];         // layer 0: K=128 -> 16 k-iters
__device__ float g_bfrag1[32 * 8 * 128];          // layer 1: K=64  ->  8 k-iters
__device__ float g_bias0[G_DIM];                  // b_ih0 + b_hh0
__device__ float g_bias1[G_DIM];                  // b_ih1 + b_hh1

// ---------------------------------------------------------------------------
// Small PTX helpers
// ---------------------------------------------------------------------------
__device__ __forceinline__ uint32_t f2tf32(float x) {
    uint32_t u;
    asm("cvt.rna.tf32.f32 %0, %1;" : "=r"(u) : "f"(x));
    return u;
}

__device__ __forceinline__ void mma_tf32(float* d, const uint32_t* a,
                                         uint32_t b0, uint32_t b1) {
    asm volatile(
        "mma.sync.aligned.m16n8k8.row.col.f32.tf32.tf32.f32 "
        "{%0,%1,%2,%3}, {%4,%5,%6,%7}, {%8,%9}, {%0,%1,%2,%3};"
        : "+f"(d[0]), "+f"(d[1]), "+f"(d[2]), "+f"(d[3])
        : "r"(a[0]), "r"(a[1]), "r"(a[2]), "r"(a[3]), "r"(b0), "r"(b1));
}

// packed fp32x2 FMA (Blackwell double-rate fp32 path; PTX-only)
__device__ __forceinline__ void ffma2(unsigned long long& d,
                                      unsigned long long a,
                                      unsigned long long b) {
    asm("fma.rn.f32x2 %0, %1, %2, %0;" : "+l"(d) : "l"(a), "l"(b));
}
__device__ __forceinline__ float2 unpack2(unsigned long long v) {
    float2 r;
    asm("mov.b64 {%0, %1}, %2;" : "=f"(r.x), "=f"(r.y) : "l"(v));
    return r;
}

__device__ __forceinline__ float fast_sigmoid(float x) {
    return 1.0f / (1.0f + __expf(-x));            // robust: exp>=0
}
__device__ __forceinline__ float fast_tanh(float x) {
    float e = __expf(-2.0f * x);                  // inf-safe at both ends
    return 2.0f / (1.0f + e) - 1.0f;
}

// ---------------------------------------------------------------------------
// Prep: fold biases; build tf32 hi/lo B-fragment buffers for both GEMMs.
// B fragment (m16n8k8.row.col): b0 = W[n][k], b1 = W[n][k+4],
//   n = g*8 + lane/4, k = kit*8 + lane%4.
// ---------------------------------------------------------------------------
__global__ void prep_kernel(const float* __restrict__ Wih0,
                            const float* __restrict__ Wih1,
                            const float* __restrict__ bih0,
                            const float* __restrict__ bhh0,
                            const float* __restrict__ bih1,
                            const float* __restrict__ bhh1) {
    int tid = blockIdx.x * blockDim.x + threadIdx.x;
    if (tid < G_DIM) {
        g_bias0[tid] = bih0[tid] + bhh0[tid];
        g_bias1[tid] = bih1[tid] + bhh1[tid];
    }
    if (tid < 32 * 16 * 32) {         // layer 0 fragments (K=128, 16 k-iters)
        int lane = tid & 31, kit = (tid >> 5) & 15, g = tid >> 9;
        int n = g * 8 + (lane >> 2);
        int k = kit * 8 + (lane & 3);
        float w0 = Wih0[n * I_DIM + k];
        float w1 = Wih0[n * I_DIM + k + 4];
        uint32_t h0 = f2tf32(w0), h1 = f2tf32(w1);
        uint32_t l0 = f2tf32(w0 - __uint_as_float(h0));
        uint32_t l1 = f2tf32(w1 - __uint_as_float(h1));
        uint32_t* base = (uint32_t*)(g_bfrag0 + (g * 16 + kit) * 128);
        base[lane * 2]          = h0;
        base[lane * 2 + 1]      = h1;
        base[64 + lane * 2]     = l0;
        base[64 + lane * 2 + 1] = l1;
    }
    int t1 = tid - 32 * 16 * 32;
    if (t1 >= 0 && t1 < 32 * 8 * 32) { // layer 1 fragments (K=64, 8 k-iters)
        int lane = t1 & 31, kit = (t1 >> 5) & 7, g = t1 >> 8;
        int n = g * 8 + (lane >> 2);
        int k = kit * 8 + (lane & 3);
        float w0 = Wih1[n * H_DIM + k];
        float w1 = Wih1[n * H_DIM + k + 4];
        uint32_t h0 = f2tf32(w0), h1 = f2tf32(w1);
        uint32_t l0 = f2tf32(w0 - __uint_as_float(h0));
        uint32_t l1 = f2tf32(w1 - __uint_as_float(h1));
        uint32_t* base = (uint32_t*)(g_bfrag1 + (g * 8 + kit) * 128);
        base[lane * 2]          = h0;
        base[lane * 2 + 1]      = h1;
        base[64 + lane * 2]     = l0;
        base[64 + lane * 2 + 1] = l1;
    }
}

// ---------------------------------------------------------------------------
// GEMM: xg[M, 256] = X[M, K] @ W[256, K]^T + bias, 3xTF32 on tensor cores.
// Block tile 64(M) x 128(N); 8 warps = 4(M) x 2(N); warp tile 16 x 64.
// grid = (M/64, 2).
// ---------------------------------------------------------------------------
template <int K, int LAYER>
__global__ void __launch_bounds__(256)
gemm_xg_kernel(const float* __restrict__ Xparam) {
    constexpr int KIT = K / 8;
    constexpr int LDA = K + 4;        // bank = (4r + c) % 32 -> conflict-free frags
    __shared__ float Xs[64][LDA];

    const float* __restrict__ X =
        (LAYER == 0) ? Xparam : (const float*)g_out1;
    const float* __restrict__ bfrag =
        (LAYER == 0) ? (const float*)g_bfrag0 : (const float*)g_bfrag1;
    const float* __restrict__ bias =
        (LAYER == 0) ? (const float*)g_bias0 : (const float*)g_bias1;

    int tid = threadIdx.x;
    int warp = tid >> 5, lane = tid & 31;
    int wm = warp >> 1, wn = warp & 1;
    int m0 = blockIdx.x * 64;

    // stage X tile (coalesced float4)
    const float4* Xg = (const float4*)(X + (size_t)m0 * K);
    for (int i = tid; i < 64 * K / 4; i += 256) {
        float4 v = Xg[i];
        int r = i / (K / 4), c = (i % (K / 4)) * 4;
        *(float4*)&Xs[r][c] = v;
    }
    __syncthreads();

    float acc[8][4];
#pragma unroll
    for (int nt = 0; nt < 8; nt++)
#pragma unroll
        for (int q = 0; q < 4; q++) acc[nt][q] = 0.0f;

    int row0 = wm * 16 + (lane >> 2);
    int kc = lane & 3;
    int gbase = blockIdx.y * 16 + wn * 8;

#pragma unroll 4
    for (int kit = 0; kit < KIT; kit++) {
        int k0 = kit * 8 + kc;
        float a0 = Xs[row0][k0],     a1 = Xs[row0 + 8][k0];
        float a2 = Xs[row0][k0 + 4], a3 = Xs[row0 + 8][k0 + 4];
        uint32_t ah[4], al[4];
        ah[0] = f2tf32(a0); al[0] = f2tf32(a0 - __uint_as_float(ah[0]));
        ah[1] = f2tf32(a1); al[1] = f2tf32(a1 - __uint_as_float(ah[1]));
        ah[2] = f2tf32(a2); al[2] = f2tf32(a2 - __uint_as_float(ah[2]));
        ah[3] = f2tf32(a3); al[3] = f2tf32(a3 - __uint_as_float(ah[3]));
#pragma unroll
        for (int nt = 0; nt < 8; nt++) {
            const uint32_t* fb =
                (const uint32_t*)(bfrag + ((gbase + nt) * KIT + kit) * 128);
            uint2 bh = *(const uint2*)(fb + lane * 2);
            uint2 bl = *(const uint2*)(fb + 64 + lane * 2);
            mma_tf32(acc[nt], ah, bh.x, bh.y);   // hi * hi
            mma_tf32(acc[nt], al, bh.x, bh.y);   // lo * hi
            mma_tf32(acc[nt], ah, bl.x, bl.y);   // hi * lo
        }
    }

    // epilogue: + bias, store fp32
    int crow = m0 + wm * 16 + (lane >> 2);
#pragma unroll
    for (int nt = 0; nt < 8; nt++) {
        int n0 = (gbase + nt) * 8 + (lane & 3) * 2;
        float b0 = bias[n0], b1 = bias[n0 + 1];
        size_t base = (size_t)crow * G_DIM + n0;
        float2 v0 = make_float2(acc[nt][0] + b0, acc[nt][1] + b1);
        float2 v1 = make_float2(acc[nt][2] + b0, acc[nt][3] + b1);
        *(float2*)&g_xg[base]              = v0;
        *(float2*)&g_xg[base + 8 * G_DIM]  = v1;
    }
}

// ---------------------------------------------------------------------------
// LSTM recurrence: persistent per-block over all T steps, 8 batch rows/block.
// Thread j (0..255) owns gate column j: 8-row dot with W_hh[j][:] (registers,
// packed f32x2 over k). Gate exchange + h update via SMEM; 2 barriers/step.
// LAYER==0 writes the full h sequence; LAYER==1 writes only h_T.
// ---------------------------------------------------------------------------
template <int LAYER>
__global__ void __launch_bounds__(256, 1)
lstm_kernel(const float* __restrict__ Whh) {
    __shared__ float h_s[8][64];       // [row][k], broadcast-read in the dot
    __shared__ float gate_s[256][9];   // pad 9 -> conflict-free (gcd(9,32)=1)

    int j = threadIdx.x;
    int r0 = blockIdx.x * 8;

    // W_hh row j packed into 32 f32x2 registers
    unsigned long long Wp[32];
    {
        const float* wr = Whh + j * H_DIM;
#pragma unroll
        for (int kk = 0; kk < 32; kk++)
            Wp[kk] = *(const unsigned long long*)(wr + 2 * kk);
    }
    if (j < 64) {
#pragma unroll
        for (int r = 0; r < 8; r++) h_s[r][j] = 0.0f;
    }
    // updater role: thread j updates h-column (j&63) for rows ur0, ur0+1
    int hm = j & 63;
    int ur0 = (j >> 6) * 2;
    float c_r[2] = {0.0f, 0.0f};

    const float* xp[8];
    float xgr[8];
#pragma unroll
    for (int r = 0; r < 8; r++) {
        xp[r] = g_xg + ((size_t)(r0 + r) * T_STEPS) * G_DIM + j;
        xgr[r] = *xp[r];
        xp[r] += G_DIM;
    }
    bool isTanh = ((j >> 6) == 2);     // gate order i,f,g,o -> g uses tanh

    __syncthreads();

    for (int t = 0; t < T_STEPS; t++) {
        // ---- gates pre-activation: xg + h . W_hh[j] (f32x2 over k) ----
        float pre[8];
#pragma unroll
        for (int r = 0; r < 8; r++) {
            unsigned long long acc0 = 0ull, acc1 = 0ull;
            const ulonglong2* hp = (const ulonglong2*)&h_s[r][0];
#pragma unroll
            for (int kk = 0; kk < 16; kk++) {
                ulonglong2 hh = hp[kk];
                ffma2(acc0, Wp[2 * kk],     hh.x);
                ffma2(acc1, Wp[2 * kk + 1], hh.y);
            }
            float2 s0 = unpack2(acc0), s1 = unpack2(acc1);
            pre[r] = xgr[r] + ((s0.x + s0.y) + (s1.x + s1.y));
        }
        // ---- prefetch next step's xg (full step of latency slack) ----
        if (t + 1 < T_STEPS) {
#pragma unroll
            for (int r = 0; r < 8; r++) { xgr[r] = *xp[r]; xp[r] += G_DIM; }
        }
        // ---- activation, publish gates ----
#pragma unroll
        for (int r = 0; r < 8; r++) {
            float v = isTanh ? fast_tanh(pre[r]) : fast_sigmoid(pre[r]);
            gate_s[j][r] = v;
        }
        __syncthreads();
        // ---- c/h update: all 256 threads, 2 rows each ----
        {
#pragma unroll
            for (int q = 0; q < 2; q++) {
                int r = ur0 + q;
                float iv = gate_s[hm][r];
                float fv = gate_s[hm + 64][r];
                float gv = gate_s[hm + 128][r];
                float ov = gate_s[hm + 192][r];
                float c = fmaf(fv, c_r[q], iv * gv);
                c_r[q] = c;
                float h = ov * fast_tanh(c);
                h_s[r][hm] = h;
                if (LAYER == 0) {
                    g_out1[((size_t)(r0 + r) * T_STEPS + t) * H_DIM + hm] = h;
                } else if (t == T_STEPS - 1) {
                    g_hlast[(r0 + r) * H_DIM + hm] = h;
                }
            }
        }
        __syncthreads();
    }
}

// ---------------------------------------------------------------------------
// Head: logits = relu(relu(h_last@Wproj^T+b)@Wfc1^T+b)@Wfc2^T+b
// One block per batch row; weights stay L1/L2-resident across blocks.
// ---------------------------------------------------------------------------
__global__ void __launch_bounds__(128)
head_kernel(const float* __restrict__ Wproj, const float* __restrict__ bproj,
            const float* __restrict__ Wfc1,  const float* __restrict__ bfc1,
            const float* __restrict__ Wfc2,  const float* __restrict__ bfc2,
            float* __restrict__ out) {
    __shared__ float hs[64], emb[128], hid[128];
    int t = threadIdx.x;
    int row = blockIdx.x;
    if (t < 64) hs[t] = g_hlast[row * H_DIM + t];
    __syncthreads();
    {
        const float* w = Wproj + t * H_DIM;
        float s0 = 0, s1 = 0, s2 = 0, s3 = 0;
#pragma unroll
        for (int k = 0; k < H_DIM; k += 4) {
            s0 = fmaf(w[k],     hs[k],     s0);
            s1 = fmaf(w[k + 1], hs[k + 1], s1);
            s2 = fmaf(w[k + 2], hs[k + 2], s2);
            s3 = fmaf(w[k + 3], hs[k + 3], s3);
        }
        emb[t] = fmaxf((s0 + s1) + (s2 + s3) + bproj[t], 0.0f);
    }
    __syncthreads();
    {
        const float* w = Wfc1 + t * E_DIM;
        float s0 = 0, s1 = 0, s2 = 0, s3 = 0;
#pragma unroll
        for (int k = 0; k < E_DIM; k += 4) {
            s0 = fmaf(w[k],     emb[k],     s0);
            s1 = fmaf(w[k + 1], emb[k + 1], s1);
            s2 = fmaf(w[k + 2], emb[k + 2], s2);
            s3 = fmaf(w[k + 3], emb[k + 3], s3);
        }
        hid[t] = fmaxf((s0 + s1) + (s2 + s3) + bfc1[t], 0.0f);
    }
    __syncthreads();
    if (t < C_DIM) {
        const float* w = Wfc2 + t * E_DIM;
        float s0 = 0, s1 = 0, s2 = 0, s3 = 0;
#pragma unroll
        for (int k = 0; k < E_DIM; k += 4) {
            s0 = fmaf(w[k],     hid[k],     s0);
            s1 = fmaf(w[k + 1], hid[k + 1], s1);
            s2 = fmaf(w[k + 2], hid[k + 2], s2);
            s3 = fmaf(w[k + 3], hid[k + 3], s3);
        }
        out[row * C_DIM + t] = (s0 + s1) + (s2 + s3) + bfc2[t];
    }
}

// ---------------------------------------------------------------------------
// Launch: prep -> gemm(xg0) -> lstm0 -> gemm(xg1) -> lstm1 -> head
// All stream-ordered kernel launches: graph-capturable, allocation-free.
// ---------------------------------------------------------------------------
extern "C" void kernel_launch(void* const* d_in, const int* in_sizes, int n_in,
                              void* d_out, int out_size) {
    const float* x     = (const float*)d_in[0];
    const float* Wih0  = (const float*)d_in[1];
    const float* Whh0  = (const float*)d_in[2];
    const float* bih0  = (const float*)d_in[3];
    const float* bhh0  = (const float*)d_in[4];
    const float* Wih1  = (const float*)d_in[5];
    const float* Whh1  = (const float*)d_in[6];
    const float* bih1  = (const float*)d_in[7];
    const float* bhh1  = (const float*)d_in[8];
    const float* Wproj = (const float*)d_in[9];
    const float* bproj = (const float*)d_in[10];
    const float* Wfc1  = (const float*)d_in[11];
    const float* bfc1  = (const float*)d_in[12];
    const float* Wfc2  = (const float*)d_in[13];
    const float* bfc2  = (const float*)d_in[14];
    float* out = (float*)d_out;

    prep_kernel<<<64, 512>>>(Wih0, Wih1, bih0, bhh0, bih1, bhh1);

    gemm_xg_kernel<I_DIM, 0><<<dim3(M_ROWS / 64, 2), 256>>>(x);
    lstm_kernel<0><<<B_SZ / 8, 256>>>(Whh0);

    gemm_xg_kernel<H_DIM, 1><<<dim3(M_ROWS / 64, 2), 256>>>(nullptr);
    lstm_kernel<1><<<B_SZ / 8, 256>>>(Whh1);

    head_kernel<<<B_SZ, 128>>>(Wproj, bproj, Wfc1, bfc1, Wfc2, bfc2, out);
}

// round 10
// speedup vs baseline: 1.8539x; 1.8539x over previous
#include <cuda_runtime.h>
#include <cuda_bf16.h>
#include <cstdint>

// ---------------------------------------------------------------------------
// Problem constants
//   x: [1024, 512, 128] fp32 -> logits [1024, 100] fp32
// ---------------------------------------------------------------------------
#define B_SZ    1024
#define T_STEPS 512
#define I_DIM   128
#define H_DIM   64
#define G_DIM   256                   // 4*H gate columns
#define E_DIM   128
#define C_DIM   100
#define M_ROWS  (B_SZ * T_STEPS)      // 524288

// ---------------------------------------------------------------------------
// Scratch (allocations forbidden -> __device__ globals)
// ---------------------------------------------------------------------------
__device__ float g_xg[(size_t)M_ROWS * G_DIM];    // 512 MB, reused by both layers
__device__ float g_out1[(size_t)M_ROWS * H_DIM];  // 128 MB, layer-0 hidden sequence
__device__ float g_hlast[B_SZ * H_DIM];           // layer-1 final hidden
// Pre-swizzled tf32 B-fragments (hi in first 64 floats; lo kept but unused now)
__device__ float g_bfrag0[32 * 16 * 128];         // layer 0: K=128 -> 16 k-iters
__device__ float g_bfrag1[32 * 8 * 128];          // layer 1: K=64  ->  8 k-iters
__device__ float g_bias0[G_DIM];                  // b_ih0 + b_hh0
__device__ float g_bias1[G_DIM];                  // b_ih1 + b_hh1

// ---------------------------------------------------------------------------
// Small PTX helpers
// ---------------------------------------------------------------------------
__device__ __forceinline__ uint32_t f2tf32(float x) {
    uint32_t u;
    asm("cvt.rna.tf32.f32 %0, %1;" : "=r"(u) : "f"(x));
    return u;
}

__device__ __forceinline__ void mma_tf32(float* d, const uint32_t* a,
                                         uint32_t b0, uint32_t b1) {
    asm volatile(
        "mma.sync.aligned.m16n8k8.row.col.f32.tf32.tf32.f32 "
        "{%0,%1,%2,%3}, {%4,%5,%6,%7}, {%8,%9}, {%0,%1,%2,%3};"
        : "+f"(d[0]), "+f"(d[1]), "+f"(d[2]), "+f"(d[3])
        : "r"(a[0]), "r"(a[1]), "r"(a[2]), "r"(a[3]), "r"(b0), "r"(b1));
}

__device__ __forceinline__ float frcp(float x) {      // MUFU.RCP (approx, ~2^-22)
    float r;
    asm("rcp.approx.f32 %0, %1;" : "=f"(r) : "f"(x));
    return r;
}
__device__ __forceinline__ float fast_sigmoid(float x) {
    return frcp(1.0f + __expf(-x));                   // 2 MUFU, inf-safe both ends
}
__device__ __forceinline__ float fast_tanh(float x) {
    return 2.0f * frcp(1.0f + __expf(-2.0f * x)) - 1.0f;
}

// ---------------------------------------------------------------------------
// Prep: fold biases; build tf32 B-fragment buffers for both input GEMMs.
// B fragment (m16n8k8.row.col): b0 = W[n][k], b1 = W[n][k+4],
//   n = g*8 + lane/4, k = kit*8 + lane%4.   (layout verified in R8)
// ---------------------------------------------------------------------------
__global__ void prep_kernel(const float* __restrict__ Wih0,
                            const float* __restrict__ Wih1,
                            const float* __restrict__ bih0,
                            const float* __restrict__ bhh0,
                            const float* __restrict__ bih1,
                            const float* __restrict__ bhh1) {
    int tid = blockIdx.x * blockDim.x + threadIdx.x;
    if (tid < G_DIM) {
        g_bias0[tid] = bih0[tid] + bhh0[tid];
        g_bias1[tid] = bih1[tid] + bhh1[tid];
    }
    if (tid < 32 * 16 * 32) {         // layer 0 fragments (K=128, 16 k-iters)
        int lane = tid & 31, kit = (tid >> 5) & 15, g = tid >> 9;
        int n = g * 8 + (lane >> 2);
        int k = kit * 8 + (lane & 3);
        uint32_t* base = (uint32_t*)(g_bfrag0 + (g * 16 + kit) * 128);
        base[lane * 2]     = f2tf32(Wih0[n * I_DIM + k]);
        base[lane * 2 + 1] = f2tf32(Wih0[n * I_DIM + k + 4]);
    }
    int t1 = tid - 32 * 16 * 32;
    if (t1 >= 0 && t1 < 32 * 8 * 32) { // layer 1 fragments (K=64, 8 k-iters)
        int lane = t1 & 31, kit = (t1 >> 5) & 7, g = t1 >> 8;
        int n = g * 8 + (lane >> 2);
        int k = kit * 8 + (lane & 3);
        uint32_t* base = (uint32_t*)(g_bfrag1 + (g * 8 + kit) * 128);
        base[lane * 2]     = f2tf32(Wih1[n * H_DIM + k]);
        base[lane * 2 + 1] = f2tf32(Wih1[n * H_DIM + k + 4]);
    }
}

// ---------------------------------------------------------------------------
// GEMM: xg[M, 256] = X[M, K] @ W[256, K]^T + bias, 1xTF32 on tensor cores.
// Block tile 64(M) x 128(N); 8 warps = 4(M) x 2(N). grid = (M/64, 2).
// ---------------------------------------------------------------------------
template <int K, int LAYER>
__global__ void __launch_bounds__(256)
gemm_xg_kernel(const float* __restrict__ Xparam) {
    constexpr int KIT = K / 8;
    constexpr int LDA = K + 4;        // bank = (4r + c) % 32 -> conflict-free frags
    __shared__ float Xs[64][LDA];

    const float* __restrict__ X =
        (LAYER == 0) ? Xparam : (const float*)g_out1;
    const float* __restrict__ bfrag =
        (LAYER == 0) ? (const float*)g_bfrag0 : (const float*)g_bfrag1;
    const float* __restrict__ bias =
        (LAYER == 0) ? (const float*)g_bias0 : (const float*)g_bias1;

    int tid = threadIdx.x;
    int warp = tid >> 5, lane = tid & 31;
    int wm = warp >> 1, wn = warp & 1;
    int m0 = blockIdx.x * 64;

    const float4* Xg = (const float4*)(X + (size_t)m0 * K);
    for (int i = tid; i < 64 * K / 4; i += 256) {
        float4 v = Xg[i];
        int r = i / (K / 4), c = (i % (K / 4)) * 4;
        *(float4*)&Xs[r][c] = v;
    }
    __syncthreads();

    float acc[8][4];
#pragma unroll
    for (int nt = 0; nt < 8; nt++)
#pragma unroll
        for (int q = 0; q < 4; q++) acc[nt][q] = 0.0f;

    int row0 = wm * 16 + (lane >> 2);
    int kc = lane & 3;
    int gbase = blockIdx.y * 16 + wn * 8;

#pragma unroll 4
    for (int kit = 0; kit < KIT; kit++) {
        int k0 = kit * 8 + kc;
        uint32_t ah[4];
        ah[0] = f2tf32(Xs[row0][k0]);
        ah[1] = f2tf32(Xs[row0 + 8][k0]);
        ah[2] = f2tf32(Xs[row0][k0 + 4]);
        ah[3] = f2tf32(Xs[row0 + 8][k0 + 4]);
#pragma unroll
        for (int nt = 0; nt < 8; nt++) {
            const uint32_t* fb =
                (const uint32_t*)(bfrag + ((gbase + nt) * KIT + kit) * 128);
            uint2 bh = *(const uint2*)(fb + lane * 2);
            mma_tf32(acc[nt], ah, bh.x, bh.y);
        }
    }

    int crow = m0 + wm * 16 + (lane >> 2);
#pragma unroll
    for (int nt = 0; nt < 8; nt++) {
        int n0 = (gbase + nt) * 8 + (lane & 3) * 2;
        float b0 = bias[n0], b1 = bias[n0 + 1];
        size_t base = (size_t)crow * G_DIM + n0;
        *(float2*)&g_xg[base]             = make_float2(acc[nt][0] + b0, acc[nt][1] + b1);
        *(float2*)&g_xg[base + 8 * G_DIM] = make_float2(acc[nt][2] + b0, acc[nt][3] + b1);
    }
}

// ---------------------------------------------------------------------------
// LSTM recurrence on tensor cores. 128 persistent blocks x 8 batch rows.
// Per step: pre = xg + h @ W_hh^T via m16n8k8 tf32 (M=16 padded, a1=a3=0 so
// dead rows stay zero). W_hh fragments live in registers for all 512 steps.
// Warp w owns gate columns [32w, 32w+32) -> gate type = w>>1 (i,f,g,o).
// Gate exchange + h/c update through SMEM; exactly 2 barriers per step.
// ---------------------------------------------------------------------------
template <int LAYER>
__global__ void __launch_bounds__(256, 1)
lstm_mma_kernel(const float* __restrict__ Whh) {
    __shared__ float h_s[8][68];       // stride 68: (4r + c) % 32 distinct
    __shared__ float gate_s[8][261];   // [row][gatecol], odd-ish stride

    int tid = threadIdx.x;
    int warp = tid >> 5, lane = tid & 31;
    int r0 = blockIdx.x * 8;
    int arow = lane >> 2;              // MMA A/C row (0..7)
    int kc = lane & 3;

    // W_hh fragments (verified layout): b0=W[n][k], b1=W[n][k+4],
    // n = nbase + lane/4, k = kit*8 + lane%4. 64 regs, resident all steps.
    uint32_t wb[4][8][2];
#pragma unroll
    for (int t4 = 0; t4 < 4; t4++) {
        int n = warp * 32 + t4 * 8 + arow;
#pragma unroll
        for (int kit = 0; kit < 8; kit++) {
            int k = kit * 8 + kc;
            wb[t4][kit][0] = f2tf32(Whh[n * H_DIM + k]);
            wb[t4][kit][1] = f2tf32(Whh[n * H_DIM + k + 4]);
        }
    }
    for (int i = tid; i < 8 * 68; i += 256) ((float*)h_s)[i] = 0.0f;

    // update role: thread updates (row ur, col um) and (row ur+4, col um)
    int ur = tid >> 6;
    int um = tid & 63;
    float c0 = 0.0f, c1 = 0.0f;

    // xg streaming pointers for the 4 n-tiles this thread covers
    const float* xgp[4];
    float2 xgv[4];
#pragma unroll
    for (int t4 = 0; t4 < 4; t4++) {
        xgp[t4] = g_xg + ((size_t)(r0 + arow) * T_STEPS) * G_DIM
                + warp * 32 + t4 * 8 + kc * 2;
        xgv[t4] = *(const float2*)xgp[t4];
    }
    bool isTanh = ((warp >> 1) == 2);  // gate order i,f,g,o

    __syncthreads();

    for (int t = 0; t < T_STEPS; t++) {
        // ---- pre-gates: acc = xg ; acc += h @ W_hh^T (tensor cores) ----
        float acc[4][4];
#pragma unroll
        for (int t4 = 0; t4 < 4; t4++) {
            acc[t4][0] = xgv[t4].x; acc[t4][1] = xgv[t4].y;
            acc[t4][2] = 0.0f;      acc[t4][3] = 0.0f;
        }
#pragma unroll
        for (int kit = 0; kit < 8; kit++) {
            int k0 = kit * 8 + kc;
            uint32_t a[4];
            a[0] = f2tf32(h_s[arow][k0]);
            a[2] = f2tf32(h_s[arow][k0 + 4]);
            a[1] = 0u; a[3] = 0u;              // padded rows 8..15 = 0
#pragma unroll
            for (int t4 = 0; t4 < 4; t4++)
                mma_tf32(acc[t4], a, wb[t4][kit][0], wb[t4][kit][1]);
        }
        // ---- prefetch next step's xg (full step of latency slack) ----
        if (t + 1 < T_STEPS) {
#pragma unroll
            for (int t4 = 0; t4 < 4; t4++) {
                xgp[t4] += G_DIM;
                xgv[t4] = *(const float2*)xgp[t4];
            }
        }
        // ---- activate + publish gates ----
#pragma unroll
        for (int t4 = 0; t4 < 4; t4++) {
            int col = warp * 32 + t4 * 8 + kc * 2;
            float v0, v1;
            if (isTanh) { v0 = fast_tanh(acc[t4][0]);    v1 = fast_tanh(acc[t4][1]); }
            else        { v0 = fast_sigmoid(acc[t4][0]); v1 = fast_sigmoid(acc[t4][1]); }
            gate_s[arow][col]     = v0;
            gate_s[arow][col + 1] = v1;
        }
        __syncthreads();
        // ---- c/h update: 256 threads x 2 (row, hcol) cells ----
        {
            float iv = gate_s[ur][um],       fv = gate_s[ur][um + 64];
            float gv = gate_s[ur][um + 128], ov = gate_s[ur][um + 192];
            c0 = fmaf(fv, c0, iv * gv);
            float h0 = ov * fast_tanh(c0);
            h_s[ur][um] = h0;

            float iw = gate_s[ur + 4][um],       fw = gate_s[ur + 4][um + 64];
            float gw = gate_s[ur + 4][um + 128], ow = gate_s[ur + 4][um + 192];
            c1 = fmaf(fw, c1, iw * gw);
            float h1 = ow * fast_tanh(c1);
            h_s[ur + 4][um] = h1;

            if (LAYER == 0) {
                g_out1[((size_t)(r0 + ur) * T_STEPS + t) * H_DIM + um]     = h0;
                g_out1[((size_t)(r0 + ur + 4) * T_STEPS + t) * H_DIM + um] = h1;
            } else if (t == T_STEPS - 1) {
                g_hlast[(r0 + ur) * H_DIM + um]     = h0;
                g_hlast[(r0 + ur + 4) * H_DIM + um] = h1;
            }
        }
        __syncthreads();
    }
}

// ---------------------------------------------------------------------------
// Head: logits = relu(relu(h_last@Wproj^T+b)@Wfc1^T+b)@Wfc2^T+b
// ---------------------------------------------------------------------------
__global__ void __launch_bounds__(128)
head_kernel(const float* __restrict__ Wproj, const float* __restrict__ bproj,
            const float* __restrict__ Wfc1,  const float* __restrict__ bfc1,
            const float* __restrict__ Wfc2,  const float* __restrict__ bfc2,
            float* __restrict__ out) {
    __shared__ float hs[64], emb[128], hid[128];
    int t = threadIdx.x;
    int row = blockIdx.x;
    if (t < 64) hs[t] = g_hlast[row * H_DIM + t];
    __syncthreads();
    {
        const float* w = Wproj + t * H_DIM;
        float s0 = 0, s1 = 0, s2 = 0, s3 = 0;
#pragma unroll
        for (int k = 0; k < H_DIM; k += 4) {
            s0 = fmaf(w[k],     hs[k],     s0);
            s1 = fmaf(w[k + 1], hs[k + 1], s1);
            s2 = fmaf(w[k + 2], hs[k + 2], s2);
            s3 = fmaf(w[k + 3], hs[k + 3], s3);
        }
        emb[t] = fmaxf((s0 + s1) + (s2 + s3) + bproj[t], 0.0f);
    }
    __syncthreads();
    {
        const float* w = Wfc1 + t * E_DIM;
        float s0 = 0, s1 = 0, s2 = 0, s3 = 0;
#pragma unroll
        for (int k = 0; k < E_DIM; k += 4) {
            s0 = fmaf(w[k],     emb[k],     s0);
            s1 = fmaf(w[k + 1], emb[k + 1], s1);
            s2 = fmaf(w[k + 2], emb[k + 2], s2);
            s3 = fmaf(w[k + 3], emb[k + 3], s3);
        }
        hid[t] = fmaxf((s0 + s1) + (s2 + s3) + bfc1[t], 0.0f);
    }
    __syncthreads();
    if (t < C_DIM) {
        const float* w = Wfc2 + t * E_DIM;
        float s0 = 0, s1 = 0, s2 = 0, s3 = 0;
#pragma unroll
        for (int k = 0; k < E_DIM; k += 4) {
            s0 = fmaf(w[k],     hid[k],     s0);
            s1 = fmaf(w[k + 1], hid[k + 1], s1);
            s2 = fmaf(w[k + 2], hid[k + 2], s2);
            s3 = fmaf(w[k + 3], hid[k + 3], s3);
        }
        out[row * C_DIM + t] = (s0 + s1) + (s2 + s3) + bfc2[t];
    }
}

// ---------------------------------------------------------------------------
// Launch: prep -> gemm(xg0) -> lstm0 -> gemm(xg1) -> lstm1 -> head
// ---------------------------------------------------------------------------
extern "C" void kernel_launch(void* const* d_in, const int* in_sizes, int n_in,
                              void* d_out, int out_size) {
    const float* x     = (const float*)d_in[0];
    const float* Wih0  = (const float*)d_in[1];
    const float* Whh0  = (const float*)d_in[2];
    const float* bih0  = (const float*)d_in[3];
    const float* bhh0  = (const float*)d_in[4];
    const float* Wih1  = (const float*)d_in[5];
    const float* Whh1  = (const float*)d_in[6];
    const float* bih1  = (const float*)d_in[7];
    const float* bhh1  = (const float*)d_in[8];
    const float* Wproj = (const float*)d_in[9];
    const float* bproj = (const float*)d_in[10];
    const float* Wfc1  = (const float*)d_in[11];
    const float* bfc1  = (const float*)d_in[12];
    const float* Wfc2  = (const float*)d_in[13];
    const float* bfc2  = (const float*)d_in[14];
    float* out = (float*)d_out;

    prep_kernel<<<64, 512>>>(Wih0, Wih1, bih0, bhh0, bih1, bhh1);

    gemm_xg_kernel<I_DIM, 0><<<dim3(M_ROWS / 64, 2), 256>>>(x);
    lstm_mma_kernel<0><<<B_SZ / 8, 256>>>(Whh0);

    gemm_xg_kernel<H_DIM, 1><<<dim3(M_ROWS / 64, 2), 256>>>(nullptr);
    lstm_mma_kernel<1><<<B_SZ / 8, 256>>>(Whh1);

    head_kernel<<<B_SZ, 128>>>(Wproj, bproj, Wfc1, bfc1, Wfc2, bfc2, out);
}

// round 13
// speedup vs baseline: 2.2598x; 1.2189x over previous
#include <cuda_runtime.h>
#include <cuda_bf16.h>
#include <cstdint>

// ---------------------------------------------------------------------------
// Problem constants
//   x: [1024, 512, 128] fp32 -> logits [1024, 100] fp32
// ---------------------------------------------------------------------------
#define B_SZ    1024
#define T_STEPS 512
#define I_DIM   128
#define H_DIM   64
#define G_DIM   256                   // 4*H gate columns
#define E_DIM   128
#define C_DIM   100
#define M_ROWS  (B_SZ * T_STEPS)      // 524288

// ---------------------------------------------------------------------------
// Scratch (allocations forbidden -> __device__ globals)
// ---------------------------------------------------------------------------
__device__ float g_xg[(size_t)M_ROWS * G_DIM];    // 512 MB, layer-0 pre-gates
__device__ float g_out1[(size_t)M_ROWS * H_DIM];  // 128 MB, layer-0 hidden sequence
__device__ float g_hlast[B_SZ * H_DIM];           // layer-1 final hidden
__device__ float g_bfrag0[32 * 16 * 128];         // tf32 B-frags for gemm0 (layout verified)
__device__ float g_bias0[G_DIM];                  // b_ih0 + b_hh0
__device__ float g_bias1[G_DIM];                  // b_ih1 + b_hh1

// ---------------------------------------------------------------------------
// Small PTX helpers
// ---------------------------------------------------------------------------
__device__ __forceinline__ uint32_t f2tf32(float x) {
    uint32_t u;
    asm("cvt.rna.tf32.f32 %0, %1;" : "=r"(u) : "f"(x));
    return u;
}

__device__ __forceinline__ void mma_tf32(float* d, const uint32_t* a,
                                         uint32_t b0, uint32_t b1) {
    asm volatile(
        "mma.sync.aligned.m16n8k8.row.col.f32.tf32.tf32.f32 "
        "{%0,%1,%2,%3}, {%4,%5,%6,%7}, {%8,%9}, {%0,%1,%2,%3};"
        : "+f"(d[0]), "+f"(d[1]), "+f"(d[2]), "+f"(d[3])
        : "r"(a[0]), "r"(a[1]), "r"(a[2]), "r"(a[3]), "r"(b0), "r"(b1));
}

__device__ __forceinline__ float frcp(float x) {      // MUFU.RCP
    float r;
    asm("rcp.approx.f32 %0, %1;" : "=f"(r) : "f"(x));
    return r;
}
__device__ __forceinline__ float fast_sigmoid(float x) {
    return frcp(1.0f + __expf(-x));                   // ex2 + rcp, inf-safe
}
__device__ __forceinline__ float fast_tanh(float x) {
    return 2.0f * frcp(1.0f + __expf(-2.0f * x)) - 1.0f;
}

// ---------------------------------------------------------------------------
// Prep: fold biases; build tf32 B-fragment buffer for gemm0.
// B fragment (m16n8k8.row.col): b0 = W[n][k], b1 = W[n][k+4],
//   n = g*8 + lane/4, k = kit*8 + lane%4.   (layout verified R8/R9)
// ---------------------------------------------------------------------------
__global__ void prep_kernel(const float* __restrict__ Wih0,
                            const float* __restrict__ bih0,
                            const float* __restrict__ bhh0,
                            const float* __restrict__ bih1,
                            const float* __restrict__ bhh1) {
    int tid = blockIdx.x * blockDim.x + threadIdx.x;
    if (tid < G_DIM) {
        g_bias0[tid] = bih0[tid] + bhh0[tid];
        g_bias1[tid] = bih1[tid] + bhh1[tid];
    }
    if (tid < 32 * 16 * 32) {         // K=128 -> 16 k-iters, 32 gate groups
        int lane = tid & 31, kit = (tid >> 5) & 15, g = tid >> 9;
        int n = g * 8 + (lane >> 2);
        int k = kit * 8 + (lane & 3);
        uint32_t* base = (uint32_t*)(g_bfrag0 + (g * 16 + kit) * 128);
        base[lane * 2]     = f2tf32(Wih0[n * I_DIM + k]);
        base[lane * 2 + 1] = f2tf32(Wih0[n * I_DIM + k + 4]);
    }
}

// ---------------------------------------------------------------------------
// GEMM0: xg[M, 256] = X[M, 128] @ W_ih0^T + bias, 1xTF32 tensor cores.
// Block tile 64(M) x 128(N); 8 warps = 4(M) x 2(N). grid = (M/64, 2).
// ---------------------------------------------------------------------------
__global__ void __launch_bounds__(256)
gemm_xg0_kernel(const float* __restrict__ X) {
    constexpr int K = I_DIM, KIT = K / 8, LDA = K + 4;
    __shared__ float Xs[64][LDA];

    int tid = threadIdx.x;
    int warp = tid >> 5, lane = tid & 31;
    int wm = warp >> 1, wn = warp & 1;
    int m0 = blockIdx.x * 64;

    const float4* Xg = (const float4*)(X + (size_t)m0 * K);
    for (int i = tid; i < 64 * K / 4; i += 256) {
        float4 v = Xg[i];
        int r = i / (K / 4), c = (i % (K / 4)) * 4;
        *(float4*)&Xs[r][c] = v;
    }
    __syncthreads();

    float acc[8][4];
#pragma unroll
    for (int nt = 0; nt < 8; nt++)
#pragma unroll
        for (int q = 0; q < 4; q++) acc[nt][q] = 0.0f;

    int row0 = wm * 16 + (lane >> 2);
    int kc = lane & 3;
    int gbase = blockIdx.y * 16 + wn * 8;

#pragma unroll 4
    for (int kit = 0; kit < KIT; kit++) {
        int k0 = kit * 8 + kc;
        uint32_t ah[4];
        ah[0] = f2tf32(Xs[row0][k0]);
        ah[1] = f2tf32(Xs[row0 + 8][k0]);
        ah[2] = f2tf32(Xs[row0][k0 + 4]);
        ah[3] = f2tf32(Xs[row0 + 8][k0 + 4]);
#pragma unroll
        for (int nt = 0; nt < 8; nt++) {
            const uint32_t* fb =
                (const uint32_t*)(g_bfrag0 + ((gbase + nt) * KIT + kit) * 128);
            uint2 bh = *(const uint2*)(fb + lane * 2);
            mma_tf32(acc[nt], ah, bh.x, bh.y);
        }
    }

    int crow = m0 + wm * 16 + (lane >> 2);
#pragma unroll
    for (int nt = 0; nt < 8; nt++) {
        int n0 = (gbase + nt) * 8 + (lane & 3) * 2;
        float b0 = g_bias0[n0], b1 = g_bias0[n0 + 1];
        size_t base = (size_t)crow * G_DIM + n0;
        *(float2*)&g_xg[base]             = make_float2(acc[nt][0] + b0, acc[nt][1] + b1);
        *(float2*)&g_xg[base + 8 * G_DIM] = make_float2(acc[nt][2] + b0, acc[nt][3] + b1);
    }
}

// ---------------------------------------------------------------------------
// LSTM layer 0: persistent, 128 blocks x 8 batch rows, 256 threads.
// Gate-per-tile mapping: n(t4) = t4*64 + warp*8 (+ frag row) -> after the 4
// MMAs each thread holds i,f,g,o for ITS two cells (arow, hc), (arow, hc+1)
// -> in-thread cell update, no gate exchange. Double-buffered h_s ->
// exactly ONE barrier per step. W_hh frags register-resident.
// ---------------------------------------------------------------------------
__global__ void __launch_bounds__(256, 1)
lstm0_kernel(const float* __restrict__ Whh) {
    __shared__ float h_s[2][8][68];    // (4r + c) % 32 distinct -> conflict-free

    int tid = threadIdx.x;
    int warp = tid >> 5, lane = tid & 31;
    int arow = lane >> 2, kc = lane & 3;
    int r0 = blockIdx.x * 8;
    int hc = warp * 8 + 2 * kc;        // this thread's 2 h-columns: hc, hc+1

    // W_hh frags: n = t4*64 + warp*8 + arow, k = kit*8 + kc  (verified layout)
    uint32_t wb[4][8][2];
#pragma unroll
    for (int t4 = 0; t4 < 4; t4++) {
        int n = t4 * 64 + warp * 8 + arow;
#pragma unroll
        for (int kit = 0; kit < 8; kit++) {
            int k = kit * 8 + kc;
            wb[t4][kit][0] = f2tf32(Whh[n * H_DIM + k]);
            wb[t4][kit][1] = f2tf32(Whh[n * H_DIM + k + 4]);
        }
    }
    for (int i = tid; i < 2 * 8 * 68; i += 256) ((float*)h_s)[i] = 0.0f;

    float c0 = 0.0f, c1 = 0.0f;

    const float* xgp[4];
    float2 xgv[4];
#pragma unroll
    for (int t4 = 0; t4 < 4; t4++) {
        xgp[t4] = g_xg + ((size_t)(r0 + arow) * T_STEPS) * G_DIM + t4 * 64 + hc;
        xgv[t4] = *(const float2*)xgp[t4];
    }
    __syncthreads();

    int p = 0;
    for (int t = 0; t < T_STEPS; t++) {
        float acc[4][4];
#pragma unroll
        for (int t4 = 0; t4 < 4; t4++) {
            acc[t4][0] = xgv[t4].x; acc[t4][1] = xgv[t4].y;
            acc[t4][2] = 0.0f;      acc[t4][3] = 0.0f;
        }
#pragma unroll
        for (int kit = 0; kit < 8; kit++) {
            int k0 = kit * 8 + kc;
            uint32_t a[4];
            a[0] = f2tf32(h_s[p][arow][k0]);
            a[2] = f2tf32(h_s[p][arow][k0 + 4]);
            a[1] = 0u; a[3] = 0u;              // padded M rows 8..15
#pragma unroll
            for (int t4 = 0; t4 < 4; t4++)
                mma_tf32(acc[t4], a, wb[t4][kit][0], wb[t4][kit][1]);
        }
        if (t + 1 < T_STEPS) {
#pragma unroll
            for (int t4 = 0; t4 < 4; t4++) {
                xgp[t4] += G_DIM;
                xgv[t4] = *(const float2*)xgp[t4];
            }
        }
        // in-thread gates: t4 = 0:i 1:f 2:g 3:o at (arow, hc/hc+1)
        float i0 = fast_sigmoid(acc[0][0]), i1 = fast_sigmoid(acc[0][1]);
        float f0 = fast_sigmoid(acc[1][0]), f1 = fast_sigmoid(acc[1][1]);
        float gg0 = fast_tanh(acc[2][0]),   gg1 = fast_tanh(acc[2][1]);
        float o0 = fast_sigmoid(acc[3][0]), o1 = fast_sigmoid(acc[3][1]);
        c0 = fmaf(f0, c0, i0 * gg0);
        c1 = fmaf(f1, c1, i1 * gg1);
        float h0 = o0 * fast_tanh(c0);
        float h1 = o1 * fast_tanh(c1);

        h_s[p ^ 1][arow][hc]     = h0;
        h_s[p ^ 1][arow][hc + 1] = h1;
        *(float2*)&g_out1[((size_t)(r0 + arow) * T_STEPS + t) * H_DIM + hc] =
            make_float2(h0, h1);
        __syncthreads();
        p ^= 1;
    }
}

// ---------------------------------------------------------------------------
// LSTM layer 1, FUSED input GEMM: gates = [x_t | h] @ [W_ih1; W_hh1]^T + b.
// Concat K = 128 -> 16 k-iters; all 128 weight frags register-resident.
// x_t (= out1[:, t, :]) prefetched one step ahead into double-buffered x_s.
// Same in-thread update, ONE barrier per step. Writes only h_T.
// ---------------------------------------------------------------------------
__global__ void __launch_bounds__(256, 1)
lstm1_fused_kernel(const float* __restrict__ Wih, const float* __restrict__ Whh) {
    __shared__ float h_s[2][8][68];
    __shared__ float x_s[2][8][68];

    int tid = threadIdx.x;
    int warp = tid >> 5, lane = tid & 31;
    int arow = lane >> 2, kc = lane & 3;
    int r0 = blockIdx.x * 8;
    int hc = warp * 8 + 2 * kc;

    // weight frags: kit 0..7 -> W_ih1 (x part), kit 8..15 -> W_hh1 (h part)
    uint32_t wb[4][16][2];
#pragma unroll
    for (int t4 = 0; t4 < 4; t4++) {
        int n = t4 * 64 + warp * 8 + arow;
#pragma unroll
        for (int kit = 0; kit < 16; kit++) {
            const float* W = (kit < 8) ? Wih : Whh;
            int k = (kit & 7) * 8 + kc;
            wb[t4][kit][0] = f2tf32(W[n * H_DIM + k]);
            wb[t4][kit][1] = f2tf32(W[n * H_DIM + k + 4]);
        }
    }
    float2 bv[4];
#pragma unroll
    for (int t4 = 0; t4 < 4; t4++)
        bv[t4] = *(const float2*)&g_bias1[t4 * 64 + hc];

    for (int i = tid; i < 2 * 8 * 68; i += 256) ((float*)h_s)[i] = 0.0f;

    // x_s[0] <- out1[:, t=0, :]   (thread: row tid>>5, cols lane*2..+1)
    int xr = tid >> 5;
    {
        float2 v = *(const float2*)&g_out1[((size_t)(r0 + xr) * T_STEPS) * H_DIM + lane * 2];
        *(float2*)&x_s[0][xr][lane * 2] = v;
    }
    float c0 = 0.0f, c1 = 0.0f;
    __syncthreads();

    int p = 0;
    for (int t = 0; t < T_STEPS; t++) {
        float acc[4][4];
#pragma unroll
        for (int t4 = 0; t4 < 4; t4++) {
            acc[t4][0] = bv[t4].x; acc[t4][1] = bv[t4].y;
            acc[t4][2] = 0.0f;     acc[t4][3] = 0.0f;
        }
#pragma unroll
        for (int kit = 0; kit < 16; kit++) {
            int k0 = (kit & 7) * 8 + kc;
            const float* src = (kit < 8) ? &x_s[p][arow][0] : &h_s[p][arow][0];
            uint32_t a[4];
            a[0] = f2tf32(src[k0]);
            a[2] = f2tf32(src[k0 + 4]);
            a[1] = 0u; a[3] = 0u;
#pragma unroll
            for (int t4 = 0; t4 < 4; t4++)
                mma_tf32(acc[t4], a, wb[t4][kit][0], wb[t4][kit][1]);
        }
        // prefetch next x_t
        float2 xv = make_float2(0.0f, 0.0f);
        if (t + 1 < T_STEPS)
            xv = *(const float2*)&g_out1[((size_t)(r0 + xr) * T_STEPS + t + 1) * H_DIM + lane * 2];

        float i0 = fast_sigmoid(acc[0][0]), i1 = fast_sigmoid(acc[0][1]);
        float f0 = fast_sigmoid(acc[1][0]), f1 = fast_sigmoid(acc[1][1]);
        float gg0 = fast_tanh(acc[2][0]),   gg1 = fast_tanh(acc[2][1]);
        float o0 = fast_sigmoid(acc[3][0]), o1 = fast_sigmoid(acc[3][1]);
        c0 = fmaf(f0, c0, i0 * gg0);
        c1 = fmaf(f1, c1, i1 * gg1);
        float h0 = o0 * fast_tanh(c0);
        float h1 = o1 * fast_tanh(c1);

        h_s[p ^ 1][arow][hc]     = h0;
        h_s[p ^ 1][arow][hc + 1] = h1;
        *(float2*)&x_s[p ^ 1][xr][lane * 2] = xv;
        if (t == T_STEPS - 1)
            *(float2*)&g_hlast[(r0 + arow) * H_DIM + hc] = make_float2(h0, h1);
        __syncthreads();
        p ^= 1;
    }
}

// ---------------------------------------------------------------------------
// Head: logits = relu(relu(h_last@Wproj^T+b)@Wfc1^T+b)@Wfc2^T+b
// ---------------------------------------------------------------------------
__global__ void __launch_bounds__(128)
head_kernel(const float* __restrict__ Wproj, const float* __restrict__ bproj,
            const float* __restrict__ Wfc1,  const float* __restrict__ bfc1,
            const float* __restrict__ Wfc2,  const float* __restrict__ bfc2,
            float* __restrict__ out) {
    __shared__ float hs[64], emb[128], hid[128];
    int t = threadIdx.x;
    int row = blockIdx.x;
    if (t < 64) hs[t] = g_hlast[row * H_DIM + t];
    __syncthreads();
    {
        const float* w = Wproj + t * H_DIM;
        float s0 = 0, s1 = 0, s2 = 0, s3 = 0;
#pragma unroll
        for (int k = 0; k < H_DIM; k += 4) {
            s0 = fmaf(w[k],     hs[k],     s0);
            s1 = fmaf(w[k + 1], hs[k + 1], s1);
            s2 = fmaf(w[k + 2], hs[k + 2], s2);
            s3 = fmaf(w[k + 3], hs[k + 3], s3);
        }
        emb[t] = fmaxf((s0 + s1) + (s2 + s3) + bproj[t], 0.0f);
    }
    __syncthreads();
    {
        const float* w = Wfc1 + t * E_DIM;
        float s0 = 0, s1 = 0, s2 = 0, s3 = 0;
#pragma unroll
        for (int k = 0; k < E_DIM; k += 4) {
            s0 = fmaf(w[k],     emb[k],     s0);
            s1 = fmaf(w[k + 1], emb[k + 1], s1);
            s2 = fmaf(w[k + 2], emb[k + 2], s2);
            s3 = fmaf(w[k + 3], emb[k + 3], s3);
        }
        hid[t] = fmaxf((s0 + s1) + (s2 + s3) + bfc1[t], 0.0f);
    }
    __syncthreads();
    if (t < C_DIM) {
        const float* w = Wfc2 + t * E_DIM;
        float s0 = 0, s1 = 0, s2 = 0, s3 = 0;
#pragma unroll
        for (int k = 0; k < E_DIM; k += 4) {
            s0 = fmaf(w[k],     hid[k],     s0);
            s1 = fmaf(w[k + 1], hid[k + 1], s1);
            s2 = fmaf(w[k + 2], hid[k + 2], s2);
            s3 = fmaf(w[k + 3], hid[k + 3], s3);
        }
        out[row * C_DIM + t] = (s0 + s1) + (s2 + s3) + bfc2[t];
    }
}

// ---------------------------------------------------------------------------
// Launch: prep -> gemm0 -> lstm0 -> lstm1(fused) -> head
// ---------------------------------------------------------------------------
extern "C" void kernel_launch(void* const* d_in, const int* in_sizes, int n_in,
                              void* d_out, int out_size) {
    const float* x     = (const float*)d_in[0];
    const float* Wih0  = (const float*)d_in[1];
    const float* Whh0  = (const float*)d_in[2];
    const float* bih0  = (const float*)d_in[3];
    const float* bhh0  = (const float*)d_in[4];
    const float* Wih1  = (const float*)d_in[5];
    const float* Whh1  = (const float*)d_in[6];
    const float* bih1  = (const float*)d_in[7];
    const float* bhh1  = (const float*)d_in[8];
    const float* Wproj = (const float*)d_in[9];
    const float* bproj = (const float*)d_in[10];
    const float* Wfc1  = (const float*)d_in[11];
    const float* bfc1  = (const float*)d_in[12];
    const float* Wfc2  = (const float*)d_in[13];
    const float* bfc2  = (const float*)d_in[14];
    float* out = (float*)d_out;

    prep_kernel<<<64, 512>>>(Wih0, bih0, bhh0, bih1, bhh1);

    gemm_xg0_kernel<<<dim3(M_ROWS / 64, 2), 256>>>(x);
    lstm0_kernel<<<B_SZ / 8, 256>>>(Whh0);
    lstm1_fused_kernel<<<B_SZ / 8, 256>>>(Wih1, Whh1);

    head_kernel<<<B_SZ, 128>>>(Wproj, bproj, Wfc1, bfc1, Wfc2, bfc2, out);
}